// round 2
// baseline (speedup 1.0000x reference)
#include <cuda_runtime.h>

#define NN 100000
#define EE 1600000
#define ETOT (EE + NN)      // edges + self loops
#define FH 128              // heads*channels for layers 0/1
#define CC 32               // channels per head
#define NCLS 40

// ---------------- scratch (device globals; no allocation allowed) ------------
__device__ __align__(16) float g_h[NN * FH];      // transformed features (x @ W)
__device__ __align__(16) float g_agg[NN * FH];    // aggregation accumulator
__device__ __align__(16) float g_feat[NN * FH];   // layer output features
__device__ __align__(16) float g_e[(size_t)ETOT * 4];   // per-edge per-head weights
__device__ __align__(16) float g_as[NN * 4];
__device__ __align__(16) float g_ad[NN * 4];
__device__ __align__(16) float g_m[NN * 4];
__device__ __align__(16) float g_den[NN * 4];
__device__ int   g_src[ETOT];
__device__ int   g_dst[ETOT];
__device__ int   g_is64;

static inline int cdiv(int a, int b) { return (a + b - 1) / b; }

// ---------------- helpers ----------------------------------------------------
__device__ __forceinline__ void atomicMaxF(float* addr, float v) {
    if (v >= 0.0f)
        atomicMax((int*)addr, __float_as_int(v));
    else
        atomicMin((unsigned int*)addr, __float_as_uint(v));
}

// ---------------- kernels ----------------------------------------------------
// Decide whether the edge_index buffer is int64 (odd 32-bit words all zero,
// since node ids < 2^31) or int32. Deterministic pure function of the input.
__global__ void detect_dtype(const int* __restrict__ e) {
    if (blockIdx.x != 0 || threadIdx.x != 0) return;
    int any = 0;
    #pragma unroll 4
    for (int i = 0; i < 4096; i++) any |= e[2 * i + 1];
    g_is64 = (any == 0) ? 1 : 0;
}

__global__ void build_edges(const int* __restrict__ e) {
    int i = blockIdx.x * blockDim.x + threadIdx.x;
    if (i >= ETOT) return;
    if (i < EE) {
        if (g_is64) {  // little-endian low words of int64
            g_src[i] = e[2 * (size_t)i];
            g_dst[i] = e[2 * ((size_t)EE + i)];
        } else {
            g_src[i] = e[i];
            g_dst[i] = e[EE + i];
        }
    } else {
        g_src[i] = i - EE;
        g_dst[i] = i - EE;
    }
}

// Y[N, Kout] = X[N, KIN] @ W[KIN, Kout], block covers 32 rows x BN cols
template<int KIN, int BN>
__global__ void gemm_kernel(const float* __restrict__ X, const float* __restrict__ W,
                            float* __restrict__ Y, int Kout) {
    __shared__ float sx[32 * KIN];
    __shared__ float sw[KIN * BN];
    const int r0 = blockIdx.x * 32;
    const int j0 = blockIdx.y * BN;

    const float4* Xv = (const float4*)(X + (size_t)r0 * KIN);
    float4* sxv = (float4*)sx;
    for (int i = threadIdx.x; i < 32 * KIN / 4; i += 256) sxv[i] = Xv[i];

    for (int i = threadIdx.x; i < KIN * BN / 4; i += 256) {
        int k = i / (BN / 4);
        int j = (i % (BN / 4)) * 4;
        *(float4*)&sw[k * BN + j] = *(const float4*)&W[(size_t)k * Kout + j0 + j];
    }
    __syncthreads();

    constexpr int CPT = BN / 8;           // cols per thread
    const int row = threadIdx.x >> 3;     // 32 rows
    const int tg  = threadIdx.x & 7;      // 8 col groups
    float acc[CPT];
    #pragma unroll
    for (int j = 0; j < CPT; j++) acc[j] = 0.0f;

    #pragma unroll 4
    for (int k = 0; k < KIN; k++) {
        float xv = sx[row * KIN + k];
        #pragma unroll
        for (int j = 0; j < CPT; j++)
            acc[j] += xv * sw[k * BN + tg * CPT + j];
    }
    float* yrow = Y + (size_t)(r0 + row) * Kout + j0 + tg * CPT;
    #pragma unroll
    for (int j = 0; j < CPT; j++) yrow[j] = acc[j];
}

// per (node, head): alpha_s/alpha_d dots; also init m=-inf, den=0
template<int HH>
__global__ void alpha_kernel(const float* __restrict__ h,
                             const float* __restrict__ as_,
                             const float* __restrict__ ad_) {
    int idx = blockIdx.x * blockDim.x + threadIdx.x;
    if (idx >= NN * HH) return;
    int n = idx / HH, hh = idx - n * HH;
    const float* base = h + (size_t)n * (HH * CC) + hh * CC;
    float s = 0.0f, d = 0.0f;
    #pragma unroll
    for (int c = 0; c < CC; c++) {
        float v = base[c];
        s += v * as_[hh * CC + c];
        d += v * ad_[hh * CC + c];
    }
    g_as[idx] = s;
    g_ad[idx] = d;
    g_m[idx]  = __int_as_float(0xFF800000); // -inf
    g_den[idx] = 0.0f;
}

__global__ void clear_kernel(float* __restrict__ p, int n) {
    int idx = blockIdx.x * blockDim.x + threadIdx.x;
    if (idx < n) p[idx] = 0.0f;
}

template<int HH>
__global__ void edge_logit() {
    int i = blockIdx.x * blockDim.x + threadIdx.x;
    if (i >= ETOT) return;
    int s = g_src[i], d = g_dst[i];
    #pragma unroll
    for (int hh = 0; hh < HH; hh++) {
        float l = g_as[s * HH + hh] + g_ad[d * HH + hh];
        l = l > 0.0f ? l : 0.2f * l;
        g_e[(size_t)i * HH + hh] = l;
        atomicMaxF(&g_m[d * HH + hh], l);
    }
}

template<int HH>
__global__ void edge_exp() {
    int idx = blockIdx.x * blockDim.x + threadIdx.x;
    if (idx >= ETOT * HH) return;
    int i = idx / HH, hh = idx - i * HH;
    int d = g_dst[i];
    float e = __expf(g_e[idx] - g_m[d * HH + hh]);
    g_e[idx] = e;
    atomicAdd(&g_den[d * HH + hh], e);
}

template<int HH>
__global__ void edge_norm() {
    int idx = blockIdx.x * blockDim.x + threadIdx.x;
    if (idx >= ETOT * HH) return;
    int i = idx / HH, hh = idx - i * HH;
    int d = g_dst[i];
    g_e[idx] = g_e[idx] / (g_den[d * HH + hh] + 1e-16f);
}

// one thread per (edge, head, 4-channel group); vectorized atomic reduction
template<int HH>
__global__ void aggregate(const float* __restrict__ hf) {
    int idx = blockIdx.x * blockDim.x + threadIdx.x;
    if (idx >= ETOT * HH * 8) return;
    int i = idx / (HH * 8);
    int q = idx - i * (HH * 8);
    int hh = q >> 3, c4 = q & 7;
    int s = g_src[i], d = g_dst[i];
    float w = g_e[(size_t)i * HH + hh];
    float4 v = *(const float4*)&hf[((size_t)s * HH + hh) * CC + c4 * 4];
    v.x *= w; v.y *= w; v.z *= w; v.w *= w;
#if __CUDA_ARCH__ >= 900
    atomicAdd((float4*)&g_agg[((size_t)d * HH + hh) * CC + c4 * 4], v);
#else
    float* a = &g_agg[((size_t)d * HH + hh) * CC + c4 * 4];
    atomicAdd(a + 0, v.x); atomicAdd(a + 1, v.y);
    atomicAdd(a + 2, v.z); atomicAdd(a + 3, v.w);
#endif
}

__global__ void bias_relu(const float* __restrict__ b, float* __restrict__ dst,
                          int mask, int total) {
    int idx = blockIdx.x * blockDim.x + threadIdx.x;
    if (idx >= total) return;
    float v = g_agg[idx] + b[idx & mask];
    dst[idx] = v > 0.0f ? v : 0.0f;
}

__global__ void final_linear(const float* __restrict__ xin,
                             const float* __restrict__ w,
                             const float* __restrict__ b,
                             float* __restrict__ out) {
    int idx = blockIdx.x * blockDim.x + threadIdx.x;
    if (idx >= NN * NCLS) return;
    int n = idx / NCLS, j = idx - n * NCLS;
    float s = b[j];
    const float* xr = xin + (size_t)n * CC;
    #pragma unroll
    for (int k = 0; k < CC; k++) s += xr[k] * w[k * NCLS + j];
    out[idx] = s;
}

// ---------------- launch ------------------------------------------------------
extern "C" void kernel_launch(void* const* d_in, const int* in_sizes, int n_in,
                              void* d_out, int out_size) {
    const float* x   = (const float*)d_in[0];
    const int*   ei  = (const int*)d_in[1];
    const float* W0  = (const float*)d_in[2];
    const float* as0 = (const float*)d_in[3];
    const float* ad0 = (const float*)d_in[4];
    const float* b0  = (const float*)d_in[5];
    const float* W1  = (const float*)d_in[6];
    const float* as1 = (const float*)d_in[7];
    const float* ad1 = (const float*)d_in[8];
    const float* b1  = (const float*)d_in[9];
    const float* W2  = (const float*)d_in[10];
    const float* as2 = (const float*)d_in[11];
    const float* ad2 = (const float*)d_in[12];
    const float* b2  = (const float*)d_in[13];
    const float* lw  = (const float*)d_in[14];
    const float* lb  = (const float*)d_in[15];
    float* out = (float*)d_out;

    float *p_h, *p_agg, *p_feat;
    cudaGetSymbolAddress((void**)&p_h,    g_h);
    cudaGetSymbolAddress((void**)&p_agg,  g_agg);
    cudaGetSymbolAddress((void**)&p_feat, g_feat);

    const int T = 256;

    detect_dtype<<<1, 1>>>(ei);
    build_edges<<<cdiv(ETOT, T), T>>>(ei);

    // ---------------- layer 0: F_IN=128 -> 4x32, concat -----------------------
    gemm_kernel<128, 64><<<dim3(NN / 32, 2), T>>>(x, W0, p_h, 128);
    alpha_kernel<4><<<cdiv(NN * 4, T), T>>>(p_h, as0, ad0);
    clear_kernel<<<cdiv(NN * FH, T), T>>>(p_agg, NN * FH);
    edge_logit<4><<<cdiv(ETOT, T), T>>>();
    edge_exp<4><<<cdiv(ETOT * 4, T), T>>>();
    edge_norm<4><<<cdiv(ETOT * 4, T), T>>>();
    aggregate<4><<<cdiv(ETOT * 32, T), T>>>(p_h);
    bias_relu<<<cdiv(NN * FH, T), T>>>(b0, p_feat, 127, NN * FH);

    // ---------------- layer 1: 128 -> 4x32, concat ----------------------------
    gemm_kernel<128, 64><<<dim3(NN / 32, 2), T>>>(p_feat, W1, p_h, 128);
    alpha_kernel<4><<<cdiv(NN * 4, T), T>>>(p_h, as1, ad1);
    clear_kernel<<<cdiv(NN * FH, T), T>>>(p_agg, NN * FH);
    edge_logit<4><<<cdiv(ETOT, T), T>>>();
    edge_exp<4><<<cdiv(ETOT * 4, T), T>>>();
    edge_norm<4><<<cdiv(ETOT * 4, T), T>>>();
    aggregate<4><<<cdiv(ETOT * 32, T), T>>>(p_h);
    bias_relu<<<cdiv(NN * FH, T), T>>>(b1, p_feat, 127, NN * FH);

    // ---------------- layer 2: 128 -> 32, heads=1, mean -----------------------
    gemm_kernel<128, 32><<<dim3(NN / 32, 1), T>>>(p_feat, W2, p_h, 32);
    alpha_kernel<1><<<cdiv(NN, T), T>>>(p_h, as2, ad2);
    clear_kernel<<<cdiv(NN * CC, T), T>>>(p_agg, NN * CC);
    edge_logit<1><<<cdiv(ETOT, T), T>>>();
    edge_exp<1><<<cdiv(ETOT, T), T>>>();
    edge_norm<1><<<cdiv(ETOT, T), T>>>();
    aggregate<1><<<cdiv(ETOT * 8, T), T>>>(p_h);
    bias_relu<<<cdiv(NN * CC, T), T>>>(b2, p_feat, 31, NN * CC);

    // ---------------- final linear 32 -> 40 -----------------------------------
    final_linear<<<cdiv(NN * NCLS, T), T>>>(p_feat, lw, lb, out);
}

// round 4
// speedup vs baseline: 2.1669x; 2.1669x over previous
#include <cuda_runtime.h>

#define NN 100000
#define EE 1600000
#define ETOT (EE + NN)      // edges + self loops
#define FH 128              // heads*channels for layers 0/1
#define CC 32               // channels per head
#define NCLS 40
#define FULL 0xffffffffu

// ---------------- scratch (device globals; no allocation allowed) ------------
__device__ __align__(16) float g_h[NN * FH];      // transformed features (x @ W)
__device__ __align__(16) float g_feat[NN * FH];   // layer output features
__device__ __align__(16) float g_e[(size_t)ETOT * 4];   // per-edge per-head exp weights (CSR order)
__device__ __align__(16) float g_as[NN * 4];
__device__ __align__(16) float g_ad[NN * 4];
__device__ __align__(16) float g_den[NN * 4];
__device__ int   g_src[ETOT];
__device__ int   g_dst[ETOT];
__device__ int   g_csrc[ETOT];        // CSR: src per edge, grouped by dst
__device__ int   g_deg[NN];
__device__ int   g_rowptr[NN + 1];
__device__ int   g_cursor[NN];
__device__ int   g_bsum[128];
__device__ int   g_boff[128];
__device__ int   g_is64;

#define SCAN_CHUNK 1024
#define NB ((NN + SCAN_CHUNK - 1) / SCAN_CHUNK)   // 98

static inline int cdiv(int a, int b) { return (a + b - 1) / b; }

// ================= edge ingestion + CSR build =================================
__global__ void detect_dtype(const int* __restrict__ e) {
    if (blockIdx.x != 0 || threadIdx.x != 0) return;
    int any = 0;
    for (int i = 0; i < 4096; i++) any |= e[2 * i + 1];
    g_is64 = (any == 0) ? 1 : 0;
}

__global__ void clear_deg() {
    int i = blockIdx.x * blockDim.x + threadIdx.x;
    if (i < NN) g_deg[i] = 0;
}

__global__ void build_edges(const int* __restrict__ e) {
    int i = blockIdx.x * blockDim.x + threadIdx.x;
    if (i >= ETOT) return;
    int s, d;
    if (i < EE) {
        if (g_is64) { s = e[2 * (size_t)i]; d = e[2 * ((size_t)EE + i)]; }
        else        { s = e[i];             d = e[EE + i]; }
    } else {
        s = i - EE; d = i - EE;
    }
    g_src[i] = s;
    g_dst[i] = d;
    atomicAdd(&g_deg[d], 1);
}

__global__ void scan_a() {
    __shared__ int sm[256];
    int blk = blockIdx.x, tid = threadIdx.x;
    int base = blk * SCAN_CHUNK + tid * 4;
    int t = 0;
    #pragma unroll
    for (int i = 0; i < 4; i++) if (base + i < NN) t += g_deg[base + i];
    sm[tid] = t;
    __syncthreads();
    for (int o = 128; o > 0; o >>= 1) {
        if (tid < o) sm[tid] += sm[tid + o];
        __syncthreads();
    }
    if (tid == 0) g_bsum[blk] = sm[0];
}

__global__ void scan_b() {
    if (threadIdx.x != 0) return;
    int run = 0;
    for (int i = 0; i < NB; i++) { g_boff[i] = run; run += g_bsum[i]; }
}

__global__ void scan_c() {
    int blk = blockIdx.x, tid = threadIdx.x;
    int base = blk * SCAN_CHUNK + tid * 4;
    int v[4];
    #pragma unroll
    for (int i = 0; i < 4; i++) v[i] = (base + i < NN) ? g_deg[base + i] : 0;
    int tsum = v[0] + v[1] + v[2] + v[3];
    int lane = tid & 31, wid = tid >> 5;
    int inc = tsum;
    #pragma unroll
    for (int o = 1; o < 32; o <<= 1) {
        int t = __shfl_up_sync(FULL, inc, o);
        if (lane >= o) inc += t;
    }
    __shared__ int wsum[8];
    if (lane == 31) wsum[wid] = inc;
    __syncthreads();
    if (tid < 8) {
        int t = wsum[tid];
        #pragma unroll
        for (int o = 1; o < 8; o <<= 1) {
            int u = __shfl_up_sync(0xff, t, o);
            if (tid >= o) t += u;
        }
        wsum[tid] = t;
    }
    __syncthreads();
    int excl = inc - tsum + (wid > 0 ? wsum[wid - 1] : 0) + g_boff[blk];
    #pragma unroll
    for (int i = 0; i < 4; i++) {
        if (base + i < NN) { g_rowptr[base + i] = excl; g_cursor[base + i] = excl; }
        excl += v[i];
    }
    if (blk == 0 && tid == 0) g_rowptr[NN] = ETOT;
}

__global__ void scatter_csr() {
    int i = blockIdx.x * blockDim.x + threadIdx.x;
    if (i >= ETOT) return;
    int pos = atomicAdd(&g_cursor[g_dst[i]], 1);
    g_csrc[pos] = g_src[i];
}

// ================= GEMM: Y[N,Kout] = X[N,128] @ W[128,Kout] ===================
// BM=64 rows, BN cols per block; 256 threads; each thread 4 x TN outputs.
template<int BN, int TN>
__global__ void gemm64(const float* __restrict__ X, const float* __restrict__ W,
                       float* __restrict__ Y, int Kout) {
    constexpr int SXP = 68;       // padded row stride (multiple of 4 -> 16B aligned)
    constexpr int SWP = BN + 4;   // BN=64 -> 68, BN=32 -> 36 (both keep alignment)
    __shared__ float sxT[64 * SXP];   // [k][row] for the staged 64 k's
    __shared__ float sw[64 * SWP];    // [k][col]
    const int tid = threadIdx.x;
    const int r0 = blockIdx.x * 64;
    const int j0 = blockIdx.y * BN;

    const int rg = (tid >> 4) * 4;
    const int cg = (tid & 15) * TN;
    float acc[4][TN];
    #pragma unroll
    for (int i = 0; i < 4; i++)
        #pragma unroll
        for (int j = 0; j < TN; j++) acc[i][j] = 0.0f;

    for (int kk = 0; kk < 128; kk += 64) {
        // X tile transposed: 64 rows x 64 k, scalar coalesced on global
        for (int idx = tid; idx < 64 * 64; idx += 256) {
            int k = idx & 63;
            int r = idx >> 6;
            int row = r0 + r; if (row >= NN) row = NN - 1;
            sxT[k * SXP + r] = X[(size_t)row * 128 + kk + k];
        }
        // W tile: 64 k x BN cols, float4
        for (int idx = tid; idx < 64 * BN / 4; idx += 256) {
            int k = idx / (BN / 4);
            int jq = (idx % (BN / 4)) * 4;
            *(float4*)&sw[k * SWP + jq] =
                *(const float4*)&W[(size_t)(kk + k) * Kout + j0 + jq];
        }
        __syncthreads();

        #pragma unroll 8
        for (int k = 0; k < 64; k++) {
            float4 a = *(const float4*)&sxT[k * SXP + rg];
            if constexpr (TN == 4) {
                float4 b = *(const float4*)&sw[k * SWP + cg];
                acc[0][0] += a.x * b.x; acc[0][1] += a.x * b.y; acc[0][2] += a.x * b.z; acc[0][3] += a.x * b.w;
                acc[1][0] += a.y * b.x; acc[1][1] += a.y * b.y; acc[1][2] += a.y * b.z; acc[1][3] += a.y * b.w;
                acc[2][0] += a.z * b.x; acc[2][1] += a.z * b.y; acc[2][2] += a.z * b.z; acc[2][3] += a.z * b.w;
                acc[3][0] += a.w * b.x; acc[3][1] += a.w * b.y; acc[3][2] += a.w * b.z; acc[3][3] += a.w * b.w;
            } else {
                float2 b = *(const float2*)&sw[k * SWP + cg];
                acc[0][0] += a.x * b.x; acc[0][1] += a.x * b.y;
                acc[1][0] += a.y * b.x; acc[1][1] += a.y * b.y;
                acc[2][0] += a.z * b.x; acc[2][1] += a.z * b.y;
                acc[3][0] += a.w * b.x; acc[3][1] += a.w * b.y;
            }
        }
        __syncthreads();
    }

    #pragma unroll
    for (int i = 0; i < 4; i++) {
        int row = r0 + rg + i;
        if (row < NN) {
            if constexpr (TN == 4) {
                float4 o = {acc[i][0], acc[i][1], acc[i][2], acc[i][3]};
                *(float4*)&Y[(size_t)row * Kout + j0 + cg] = o;
            } else {
                float2 o = {acc[i][0], acc[i][1]};
                *(float2*)&Y[(size_t)row * Kout + j0 + cg] = o;
            }
        }
    }
}

// ================= alpha dots: warp per node ===================================
template<int HH>
__global__ void alpha_kernel(const float* __restrict__ h,
                             const float* __restrict__ as_,
                             const float* __restrict__ ad_) {
    int warp = (blockIdx.x * blockDim.x + threadIdx.x) >> 5;
    int lane = threadIdx.x & 31;
    if (warp >= NN) return;
    if constexpr (HH == 4) {
        float4 v = *(const float4*)&h[(size_t)warp * 128 + lane * 4];
        int hh = lane >> 3;
        int c0 = (lane & 7) * 4;
        float4 a = *(const float4*)&as_[hh * 32 + c0];
        float4 b = *(const float4*)&ad_[hh * 32 + c0];
        float s = v.x * a.x + v.y * a.y + v.z * a.z + v.w * a.w;
        float d = v.x * b.x + v.y * b.y + v.z * b.z + v.w * b.w;
        #pragma unroll
        for (int o = 4; o >= 1; o >>= 1) {
            s += __shfl_xor_sync(FULL, s, o);
            d += __shfl_xor_sync(FULL, d, o);
        }
        if ((lane & 7) == 0) { g_as[warp * 4 + hh] = s; g_ad[warp * 4 + hh] = d; }
    } else {
        float v = h[(size_t)warp * 32 + lane];
        float s = v * as_[lane], d = v * ad_[lane];
        #pragma unroll
        for (int o = 16; o >= 1; o >>= 1) {
            s += __shfl_xor_sync(FULL, s, o);
            d += __shfl_xor_sync(FULL, d, o);
        }
        if (lane == 0) { g_as[warp] = s; g_ad[warp] = d; }
    }
}

// ================= segment softmax over in-edges: warp per node ================
__device__ __forceinline__ float leaky(float x) { return x > 0.0f ? x : 0.2f * x; }

template<int HH>
__global__ void csr_softmax() {
    int warp = (blockIdx.x * blockDim.x + threadIdx.x) >> 5;
    int lane = threadIdx.x & 31;
    if (warp >= NN) return;
    int off = g_rowptr[warp];
    int deg = g_rowptr[warp + 1] - off;

    if constexpr (HH == 4) {
        float4 adv = *(const float4*)&g_ad[warp * 4];
        float mx = -1e30f, my = -1e30f, mz = -1e30f, mw = -1e30f;
        for (int e = lane; e < deg; e += 32) {
            int s = g_csrc[off + e];
            float4 a = *(const float4*)&g_as[s * 4];
            mx = fmaxf(mx, leaky(a.x + adv.x));
            my = fmaxf(my, leaky(a.y + adv.y));
            mz = fmaxf(mz, leaky(a.z + adv.z));
            mw = fmaxf(mw, leaky(a.w + adv.w));
        }
        #pragma unroll
        for (int o = 16; o >= 1; o >>= 1) {
            mx = fmaxf(mx, __shfl_xor_sync(FULL, mx, o));
            my = fmaxf(my, __shfl_xor_sync(FULL, my, o));
            mz = fmaxf(mz, __shfl_xor_sync(FULL, mz, o));
            mw = fmaxf(mw, __shfl_xor_sync(FULL, mw, o));
        }
        float dx = 0, dy = 0, dz = 0, dw = 0;
        for (int e = lane; e < deg; e += 32) {
            int s = g_csrc[off + e];
            float4 a = *(const float4*)&g_as[s * 4];
            float4 ex;
            ex.x = __expf(leaky(a.x + adv.x) - mx);
            ex.y = __expf(leaky(a.y + adv.y) - my);
            ex.z = __expf(leaky(a.z + adv.z) - mz);
            ex.w = __expf(leaky(a.w + adv.w) - mw);
            *(float4*)&g_e[(size_t)(off + e) * 4] = ex;
            dx += ex.x; dy += ex.y; dz += ex.z; dw += ex.w;
        }
        #pragma unroll
        for (int o = 16; o >= 1; o >>= 1) {
            dx += __shfl_xor_sync(FULL, dx, o);
            dy += __shfl_xor_sync(FULL, dy, o);
            dz += __shfl_xor_sync(FULL, dz, o);
            dw += __shfl_xor_sync(FULL, dw, o);
        }
        if (lane == 0) {
            float4 dn = {dx, dy, dz, dw};
            *(float4*)&g_den[warp * 4] = dn;
        }
    } else {
        float adv = g_ad[warp];
        float m = -1e30f;
        for (int e = lane; e < deg; e += 32)
            m = fmaxf(m, leaky(g_as[g_csrc[off + e]] + adv));
        #pragma unroll
        for (int o = 16; o >= 1; o >>= 1) m = fmaxf(m, __shfl_xor_sync(FULL, m, o));
        float dsum = 0;
        for (int e = lane; e < deg; e += 32) {
            float ex = __expf(leaky(g_as[g_csrc[off + e]] + adv) - m);
            g_e[off + e] = ex;
            dsum += ex;
        }
        #pragma unroll
        for (int o = 16; o >= 1; o >>= 1) dsum += __shfl_xor_sync(FULL, dsum, o);
        if (lane == 0) g_den[warp] = dsum;
    }
}

// ================= pull aggregation: warp per (node, head) =====================
// acc = sum_e w_e * h[src_e], then /den + bias + relu, write g_feat. No atomics.
template<int HH>
__global__ void csr_aggregate(const float* __restrict__ hf,
                              const float* __restrict__ bias) {
    int gw = (blockIdx.x * blockDim.x + threadIdx.x) >> 5;
    int lane = threadIdx.x & 31;
    if (gw >= NN * HH) return;
    int n = gw / HH, hh = gw - n * HH;
    int off = g_rowptr[n];
    int deg = g_rowptr[n + 1] - off;

    float acc = 0.0f;
    for (int base = 0; base < deg; base += 32) {
        int e = base + lane;
        int s = 0; float w = 0.0f;
        if (e < deg) {
            int p = off + e;
            s = g_csrc[p];
            w = g_e[(size_t)p * HH + hh];
        }
        int cnt = min(32, deg - base);
        for (int j = 0; j < cnt; j++) {
            int   sj = __shfl_sync(FULL, s, j);
            float wj = __shfl_sync(FULL, w, j);
            acc += wj * hf[(size_t)sj * (HH * 32) + hh * 32 + lane];
        }
    }
    float den = g_den[n * HH + hh];
    float v = acc / (den + 1e-16f) + bias[hh * 32 + lane];
    g_feat[(size_t)n * (HH * 32) + hh * 32 + lane] = v > 0.0f ? v : 0.0f;
}

// ================= final linear 32 -> 40 =======================================
__global__ void final_linear(const float* __restrict__ xin,
                             const float* __restrict__ w,
                             const float* __restrict__ b,
                             float* __restrict__ out) {
    __shared__ float swt[32 * 40];
    __shared__ float sxr[64 * 33];
    int tid = threadIdx.x;
    int n0 = blockIdx.x * 64;
    for (int i = tid; i < 32 * 40; i += 256) swt[i] = w[i];
    for (int i = tid; i < 64 * 32; i += 256) {
        int n = i >> 5, c = i & 31;
        int gn = n0 + n;
        sxr[n * 33 + c] = (gn < NN) ? xin[(size_t)gn * 32 + c] : 0.0f;
    }
    __syncthreads();
    int nl = tid >> 2;
    int j0 = (tid & 3) * 10;
    int gn = n0 + nl;
    if (gn >= NN) return;
    float acc[10];
    #pragma unroll
    for (int j = 0; j < 10; j++) acc[j] = b[j0 + j];
    #pragma unroll
    for (int k = 0; k < 32; k++) {
        float xv = sxr[nl * 33 + k];
        #pragma unroll
        for (int j = 0; j < 10; j++) acc[j] += xv * swt[k * 40 + j0 + j];
    }
    #pragma unroll
    for (int j = 0; j < 10; j++) out[(size_t)gn * 40 + j0 + j] = acc[j];
}

// ================= launch ======================================================
extern "C" void kernel_launch(void* const* d_in, const int* in_sizes, int n_in,
                              void* d_out, int out_size) {
    const float* x   = (const float*)d_in[0];
    const int*   ei  = (const int*)d_in[1];
    const float* W0  = (const float*)d_in[2];
    const float* as0 = (const float*)d_in[3];
    const float* ad0 = (const float*)d_in[4];
    const float* b0  = (const float*)d_in[5];
    const float* W1  = (const float*)d_in[6];
    const float* as1 = (const float*)d_in[7];
    const float* ad1 = (const float*)d_in[8];
    const float* b1  = (const float*)d_in[9];
    const float* W2  = (const float*)d_in[10];
    const float* as2 = (const float*)d_in[11];
    const float* ad2 = (const float*)d_in[12];
    const float* b2  = (const float*)d_in[13];
    const float* lw  = (const float*)d_in[14];
    const float* lb  = (const float*)d_in[15];
    float* out = (float*)d_out;

    float *p_h, *p_feat;
    cudaGetSymbolAddress((void**)&p_h,    g_h);
    cudaGetSymbolAddress((void**)&p_feat, g_feat);

    const int T = 256;
    const int WPB = T / 32;   // warps per block

    // ---- CSR build (once) ----
    detect_dtype<<<1, 32>>>(ei);
    clear_deg<<<cdiv(NN, T), T>>>();
    build_edges<<<cdiv(ETOT, T), T>>>(ei);
    scan_a<<<NB, 256>>>();
    scan_b<<<1, 32>>>();
    scan_c<<<NB, 256>>>();
    scatter_csr<<<cdiv(ETOT, T), T>>>();

    // ---- layer 0: 128 -> 4x32, concat ----
    gemm64<64, 4><<<dim3(cdiv(NN, 64), 2), T>>>(x, W0, p_h, 128);
    alpha_kernel<4><<<cdiv(NN, WPB), T>>>(p_h, as0, ad0);
    csr_softmax<4><<<cdiv(NN, WPB), T>>>();
    csr_aggregate<4><<<cdiv(NN * 4, WPB), T>>>(p_h, b0);

    // ---- layer 1: 128 -> 4x32, concat ----
    gemm64<64, 4><<<dim3(cdiv(NN, 64), 2), T>>>(p_feat, W1, p_h, 128);
    alpha_kernel<4><<<cdiv(NN, WPB), T>>>(p_h, as1, ad1);
    csr_softmax<4><<<cdiv(NN, WPB), T>>>();
    csr_aggregate<4><<<cdiv(NN * 4, WPB), T>>>(p_h, b1);

    // ---- layer 2: 128 -> 32, heads=1, mean(=identity) ----
    gemm64<32, 2><<<dim3(cdiv(NN, 64), 1), T>>>(p_feat, W2, p_h, 32);
    alpha_kernel<1><<<cdiv(NN, WPB), T>>>(p_h, as2, ad2);
    csr_softmax<1><<<cdiv(NN, WPB), T>>>();
    csr_aggregate<1><<<cdiv(NN, WPB), T>>>(p_h, b2);

    // ---- final linear 32 -> 40 ----
    final_linear<<<cdiv(NN, 64), T>>>(p_feat, lw, lb, out);
}